// round 4
// baseline (speedup 1.0000x reference)
#include <cuda_runtime.h>

#define NMAX 50000
#define EMAX 100000

// ---------------- device scratch (static allocation, allowed) ----------------
__device__ float g_v[2][NMAX * 512];      // v_user, v_item
__device__ float g_a[4][NMAX * 8];        // aq_u, ak_u, aq_i, ak_i
__device__ float g_weff[4][8 * 256];      // effective attn-scalar weights
__device__ float g_beff[4][8];            // effective attn-scalar biases
__device__ float g_num[3][NMAX * 512];    // per-etype message accumulators
__device__ float g_den[3][NMAX * 8];      // per-etype softmax denominators
__device__ float g_deg[3][NMAX];          // per-etype in-degree
__device__ float g_w[3][EMAX * 8];        // per-edge exp(score) per head

// ---------------- effective weights: weff[t][h][k] = sum_d W[h*64+d][k]*wa[d]
__global__ void weff_kernel(const float* __restrict__ Wq_u, const float* __restrict__ Wk_u,
                            const float* __restrict__ Wq_i, const float* __restrict__ Wk_i,
                            const float* __restrict__ bq_u, const float* __restrict__ bk_u,
                            const float* __restrict__ bq_i, const float* __restrict__ bk_i,
                            const float* __restrict__ wa_u, const float* __restrict__ wa_i)
{
    int b = blockIdx.x;
    if (b < 32) {
        int t = b >> 3, h = b & 7;
        const float* W  = (t == 0) ? Wq_u : (t == 1) ? Wk_u : (t == 2) ? Wq_i : Wk_i;
        const float* wa = (t < 2) ? wa_u : wa_i;
        __shared__ float was[64];
        if (threadIdx.x < 64) was[threadIdx.x] = wa[threadIdx.x];
        __syncthreads();
        int k = threadIdx.x;
        float acc = 0.f;
        #pragma unroll 8
        for (int d = 0; d < 64; d++)
            acc += W[(h * 64 + d) * 256 + k] * was[d];
        g_weff[t][h * 256 + k] = acc;
    } else {
        if (threadIdx.x < 32) {
            int t = threadIdx.x >> 3, h = threadIdx.x & 7;
            const float* bb = (t == 0) ? bq_u : (t == 1) ? bk_u : (t == 2) ? bq_i : bk_i;
            const float* wa = (t < 2) ? wa_u : wa_i;
            float acc = 0.f;
            for (int d = 0; d < 64; d++) acc += bb[h * 64 + d] * wa[d];
            g_beff[t][h] = acc;
        }
    }
}

// ---------------- zero accumulators ----------------
__global__ void zero_kernel()
{
    long long idx = (long long)blockIdx.x * blockDim.x + threadIdx.x;
    long long stride = (long long)gridDim.x * blockDim.x;
    float4 z = make_float4(0.f, 0.f, 0.f, 0.f);
    float4* p = (float4*)&g_num[0][0];
    long long n = (long long)3 * NMAX * 512 / 4;
    for (long long i = idx; i < n; i += stride) p[i] = z;
    float4* p2 = (float4*)&g_den[0][0];
    long long n2 = (long long)3 * NMAX * 8 / 4;
    for (long long i = idx; i < n2; i += stride) p2[i] = z;
    float* p3 = &g_deg[0][0];
    long long n3 = (long long)3 * NMAX;
    for (long long i = idx; i < n3; i += stride) p3[i] = 0.f;
}

// ---------------- V projection: C[M,512] = A[M,256] @ W[512,256]^T + b ------
__global__ void __launch_bounds__(256) sgemm_kernel(const float* __restrict__ A,
        const float* __restrict__ W, const float* __restrict__ bias,
        int item, int M)
{
    const int K = 256, N = 512;
    __shared__ float As[8][128];
    __shared__ float Bs[8][128];
    float* C = item ? g_v[1] : g_v[0];
    int tid = threadIdx.x;
    int mbase = blockIdx.y * 128, nbase = blockIdx.x * 128;
    int lrow = tid >> 1, lcol = (tid & 1) * 4;
    int tr = (tid >> 4) * 8, tc = (tid & 15) * 8;
    float acc[8][8];
    #pragma unroll
    for (int i = 0; i < 8; i++)
        #pragma unroll
        for (int j = 0; j < 8; j++) acc[i][j] = 0.f;

    for (int k0 = 0; k0 < K; k0 += 8) {
        float4 av = make_float4(0.f, 0.f, 0.f, 0.f);
        int gm = mbase + lrow;
        if (gm < M) av = *(const float4*)(A + (long long)gm * K + k0 + lcol);
        float4 wv = *(const float4*)(W + (nbase + lrow) * K + k0 + lcol);
        As[lcol + 0][lrow] = av.x; As[lcol + 1][lrow] = av.y;
        As[lcol + 2][lrow] = av.z; As[lcol + 3][lrow] = av.w;
        Bs[lcol + 0][lrow] = wv.x; Bs[lcol + 1][lrow] = wv.y;
        Bs[lcol + 2][lrow] = wv.z; Bs[lcol + 3][lrow] = wv.w;
        __syncthreads();
        #pragma unroll
        for (int kk = 0; kk < 8; kk++) {
            float a[8], bb[8];
            #pragma unroll
            for (int i = 0; i < 8; i++) a[i] = As[kk][tr + i];
            #pragma unroll
            for (int j = 0; j < 8; j++) bb[j] = Bs[kk][tc + j];
            #pragma unroll
            for (int i = 0; i < 8; i++)
                #pragma unroll
                for (int j = 0; j < 8; j++)
                    acc[i][j] += a[i] * bb[j];
        }
        __syncthreads();
    }
    float4 b0 = *(const float4*)(bias + nbase + tc);
    float4 b1 = *(const float4*)(bias + nbase + tc + 4);
    #pragma unroll
    for (int i = 0; i < 8; i++) {
        int gm = mbase + tr + i;
        if (gm < M) {
            float4 o0 = make_float4(acc[i][0] + b0.x, acc[i][1] + b0.y,
                                    acc[i][2] + b0.z, acc[i][3] + b0.w);
            float4 o1 = make_float4(acc[i][4] + b1.x, acc[i][5] + b1.y,
                                    acc[i][6] + b1.z, acc[i][7] + b1.w);
            *(float4*)(C + (long long)gm * N + nbase + tc) = o0;
            *(float4*)(C + (long long)gm * N + nbase + tc + 4) = o1;
        }
    }
}

// ---------------- attention scalars: a[n,h] = x[n,:].weff[t,h,:] + beff ----
__global__ void __launch_bounds__(256) attn_scalar_kernel(const float* __restrict__ x_u,
        const float* __restrict__ x_i, int NUn, int NIn)
{
    int t = blockIdx.y;                 // 0 = user, 1 = item
    int Nn = t ? NIn : NUn;
    const float* X = t ? x_i : x_u;
    __shared__ float xs[16][260];       // row stride 1040 B (16B-aligned)
    __shared__ float ws[16][260];       // row stride 1040 B (16B-aligned)
    int tid = threadIdx.x;
    int nb = blockIdx.x * 16;
    for (int i = tid; i < 16 * 256; i += 256) {
        int r = i >> 8, c = i & 255;
        ws[r][c] = g_weff[t * 2 + (r >> 3)][(r & 7) * 256 + c];
    }
    for (int i = tid; i < 16 * 64; i += 256) {
        int r = i >> 6, c = i & 63;
        float4 v = make_float4(0.f, 0.f, 0.f, 0.f);
        if (nb + r < Nn) v = *(const float4*)(X + (long long)(nb + r) * 256 + c * 4);
        *(float4*)(&xs[r][c * 4]) = v;
    }
    __syncthreads();
    int ln = tid >> 4;     // local node
    int o  = tid & 15;     // qk*8 + h
    float acc = 0.f;
    #pragma unroll 4
    for (int k = 0; k < 256; k += 4) {
        float4 xv = *(const float4*)(&xs[ln][k]);
        float4 wv = *(const float4*)(&ws[o][k]);
        acc += xv.x * wv.x + xv.y * wv.y + xv.z * wv.z + xv.w * wv.w;
    }
    int node = nb + ln;
    if (node < Nn) {
        int slice = t * 2 + (o >> 3);
        g_a[slice][node * 8 + (o & 7)] = acc + g_beff[slice][o & 7];
    }
}

// ---------------- edge pass 1: exp(score), denominators, degrees ----------
__global__ void edge1_kernel(const int* __restrict__ src, const int* __restrict__ dst,
                             int et, int sliceS, int sliceD, int E)
{
    int idx = blockIdx.x * blockDim.x + threadIdx.x;
    if (idx >= E * 8) return;
    int e = idx >> 3, h = idx & 7;
    int s = src[e], d = dst[e];
    float sc = (g_a[sliceS][s * 8 + h] + g_a[sliceD][d * 8 + h]) * 0.125f;
    float w = expf(sc);
    g_w[et][e * 8 + h] = w;
    atomicAdd(&g_den[et][d * 8 + h], w);
    if (h == 0) atomicAdd(&g_deg[et][d], 1.0f);
}

// ---------------- edge pass 2: scatter-add exp(score)*v into num ----------
// warp per edge; vectorized float4 atomics (sm_90+) -> 4x fewer REDG ops
__global__ void __launch_bounds__(256) edge2_kernel(const int* __restrict__ src,
        const int* __restrict__ dst, int et, int vsel, int E)
{
    int gw = (int)((blockIdx.x * blockDim.x + threadIdx.x) >> 5);
    int lane = threadIdx.x & 31;
    if (gw >= E) return;
    int s = __ldg(src + gw), d = __ldg(dst + gw);
    const float* vrow = g_v[vsel] + (long long)s * 512;
    float wv = 0.f;
    if (lane < 8) wv = g_w[et][gw * 8 + lane];
    float* nrow = g_num[et] + (long long)d * 512;
    #pragma unroll
    for (int c = 0; c < 4; c++) {
        int off = (c * 32 + lane) * 4;                 // 16B-aligned float offset
        float4 v = *(const float4*)(vrow + off);
        float wh = __shfl_sync(0xffffffffu, wv, off >> 6);   // head = element/64
        float4 m = make_float4(v.x * wh, v.y * wh, v.z * wh, v.w * wh);
        atomicAdd((float4*)(nrow + off), m);           // RED.E.ADD.F32 x4 vector
    }
}

// ---------------- finalize: normalize + inter-type sum, write output ------
__global__ void finalize_kernel(float* __restrict__ out, int NUn, int NIn)
{
    int idx = blockIdx.x * blockDim.x + threadIdx.x;
    int totU = NUn * 128;
    int tot = totU + NIn * 128;
    if (idx >= tot) return;
    if (idx < totU) {
        int n = idx >> 7, j = idx & 127;
        int h = j >> 4;
        float4 a = *(const float4*)(g_num[1] + (long long)n * 512 + j * 4);
        float4 b = *(const float4*)(g_num[2] + (long long)n * 512 + j * 4);
        float den1 = g_den[1][n * 8 + h], den2 = g_den[2][n * 8 + h];
        float s1 = den1 > 0.f ? 1.f / (den1 * g_deg[1][n]) : 0.f;
        float s2 = den2 > 0.f ? 1.f / (den2 * g_deg[2][n]) : 0.f;
        float4 r = make_float4(a.x * s1 + b.x * s2, a.y * s1 + b.y * s2,
                               a.z * s1 + b.z * s2, a.w * s1 + b.w * s2);
        *(float4*)(out + (long long)n * 512 + j * 4) = r;
    } else {
        int m = idx - totU;
        int n = m >> 7, j = m & 127;
        int h = j >> 4;
        float4 a = *(const float4*)(g_num[0] + (long long)n * 512 + j * 4);
        float den0 = g_den[0][n * 8 + h];
        float s0 = den0 > 0.f ? 1.f / (den0 * g_deg[0][n]) : 0.f;
        float4 r = make_float4(a.x * s0, a.y * s0, a.z * s0, a.w * s0);
        *(float4*)(out + (long long)NUn * 512 + (long long)n * 512 + j * 4) = r;
    }
}

// ---------------- launch ----------------
extern "C" void kernel_launch(void* const* d_in, const int* in_sizes, int n_in,
                              void* d_out, int out_size)
{
    const float* x_u  = (const float*)d_in[0];
    const float* x_i  = (const float*)d_in[1];
    const float* Wq_u = (const float*)d_in[2];  const float* bq_u = (const float*)d_in[3];
    const float* Wk_u = (const float*)d_in[4];  const float* bk_u = (const float*)d_in[5];
    const float* Wv_u = (const float*)d_in[6];  const float* bv_u = (const float*)d_in[7];
    const float* Wq_i = (const float*)d_in[8];  const float* bq_i = (const float*)d_in[9];
    const float* Wk_i = (const float*)d_in[10]; const float* bk_i = (const float*)d_in[11];
    const float* Wv_i = (const float*)d_in[12]; const float* bv_i = (const float*)d_in[13];
    const float* wa_u = (const float*)d_in[14];
    const float* wa_i = (const float*)d_in[15];
    const int* src_c  = (const int*)d_in[16];   const int* dst_c  = (const int*)d_in[17];
    const int* src_cb = (const int*)d_in[18];   const int* dst_cb = (const int*)d_in[19];
    const int* src_f  = (const int*)d_in[20];   const int* dst_f  = (const int*)d_in[21];
    int NUn = in_sizes[0] / 256;
    int NIn = in_sizes[1] / 256;
    int E0 = in_sizes[16], E1 = in_sizes[18], E2 = in_sizes[20];
    float* out = (float*)d_out;

    weff_kernel<<<33, 256>>>(Wq_u, Wk_u, Wq_i, Wk_i, bq_u, bk_u, bq_i, bk_i, wa_u, wa_i);
    zero_kernel<<<2048, 256>>>();
    sgemm_kernel<<<dim3(4, (NUn + 127) / 128), 256>>>(x_u, Wv_u, bv_u, 0, NUn);
    sgemm_kernel<<<dim3(4, (NIn + 127) / 128), 256>>>(x_i, Wv_i, bv_i, 1, NIn);
    int NMaxN = NUn > NIn ? NUn : NIn;
    attn_scalar_kernel<<<dim3((NMaxN + 15) / 16, 2), 256>>>(x_u, x_i, NUn, NIn);
    // clicks: src=user(ak_u=1) dst=item(aq_i=2)
    edge1_kernel<<<(E0 * 8 + 255) / 256, 256>>>(src_c, dst_c, 0, 1, 2, E0);
    // clicked_by: src=item(ak_i=3) dst=user(aq_u=0)
    edge1_kernel<<<(E1 * 8 + 255) / 256, 256>>>(src_cb, dst_cb, 1, 3, 0, E1);
    // follows: src=user(ak_u=1) dst=user(aq_u=0)
    edge1_kernel<<<(E2 * 8 + 255) / 256, 256>>>(src_f, dst_f, 2, 1, 0, E2);
    edge2_kernel<<<(E0 * 32 + 255) / 256, 256>>>(src_c, dst_c, 0, 0, E0);
    edge2_kernel<<<(E1 * 32 + 255) / 256, 256>>>(src_cb, dst_cb, 1, 1, E1);
    edge2_kernel<<<(E2 * 32 + 255) / 256, 256>>>(src_f, dst_f, 2, 0, E2);
    finalize_kernel<<<((NUn + NIn) * 128 + 255) / 256, 256>>>(out, NUn, NIn);
}

// round 9
// speedup vs baseline: 1.3646x; 1.3646x over previous
#include <cuda_runtime.h>
#include <cuda_bf16.h>
#include <cstdint>

typedef unsigned int u32;

#define NMAX 50000
#define NPAD 50176
#define EMAX 100000
#define XCSZ 38535168   /* NPAD * 768 */
#define WCSZ 393216     /* 512 * 768 */

// ---------------- device scratch (static allocation, allowed) ----------------
__device__ float g_v[2][NMAX * 512];      // v_user, v_item
__device__ float g_a[4][NMAX * 8];        // aq_u, ak_u, aq_i, ak_i
__device__ float g_weff[4][8 * 256];      // effective attn-scalar weights
__device__ float g_beff[4][8];            // effective attn-scalar biases
__device__ float g_num[3][NMAX * 512];    // per-etype message accumulators
__device__ float g_den[3][NMAX * 8];      // per-etype softmax denominators
__device__ float g_deg[3][NMAX];          // per-etype in-degree
__device__ float g_w[3][EMAX * 8];        // per-edge exp(score) per head
// bf16-split GEMM operands, K-concatenated: A' = [hi|hi|lo], W' = [hi|lo|hi]
__device__ __nv_bfloat16 g_xc[2][XCSZ];
__device__ __nv_bfloat16 g_wc[2][WCSZ];

// ---------------- effective weights: weff[t][h][k] = sum_d W[h*64+d][k]*wa[d]
__global__ void weff_kernel(const float* __restrict__ Wq_u, const float* __restrict__ Wk_u,
                            const float* __restrict__ Wq_i, const float* __restrict__ Wk_i,
                            const float* __restrict__ bq_u, const float* __restrict__ bk_u,
                            const float* __restrict__ bq_i, const float* __restrict__ bk_i,
                            const float* __restrict__ wa_u, const float* __restrict__ wa_i)
{
    int b = blockIdx.x;
    if (b < 32) {
        int t = b >> 3, h = b & 7;
        const float* W  = (t == 0) ? Wq_u : (t == 1) ? Wk_u : (t == 2) ? Wq_i : Wk_i;
        const float* wa = (t < 2) ? wa_u : wa_i;
        __shared__ float was[64];
        if (threadIdx.x < 64) was[threadIdx.x] = wa[threadIdx.x];
        __syncthreads();
        int k = threadIdx.x;
        float acc = 0.f;
        #pragma unroll 8
        for (int d = 0; d < 64; d++)
            acc += W[(h * 64 + d) * 256 + k] * was[d];
        g_weff[t][h * 256 + k] = acc;
    } else {
        if (threadIdx.x < 32) {
            int t = threadIdx.x >> 3, h = threadIdx.x & 7;
            const float* bb = (t == 0) ? bq_u : (t == 1) ? bk_u : (t == 2) ? bq_i : bk_i;
            const float* wa = (t < 2) ? wa_u : wa_i;
            float acc = 0.f;
            for (int d = 0; d < 64; d++) acc += bb[h * 64 + d] * wa[d];
            g_beff[t][h] = acc;
        }
    }
}

// ---------------- zero accumulators ----------------
__global__ void zero_kernel()
{
    long long idx = (long long)blockIdx.x * blockDim.x + threadIdx.x;
    long long stride = (long long)gridDim.x * blockDim.x;
    float4 z = make_float4(0.f, 0.f, 0.f, 0.f);
    float4* p = (float4*)&g_num[0][0];
    long long n = (long long)3 * NMAX * 512 / 4;
    for (long long i = idx; i < n; i += stride) p[i] = z;
    float4* p2 = (float4*)&g_den[0][0];
    long long n2 = (long long)3 * NMAX * 8 / 4;
    for (long long i = idx; i < n2; i += stride) p2[i] = z;
    float* p3 = &g_deg[0][0];
    long long n3 = (long long)3 * NMAX;
    for (long long i = idx; i < n3; i += stride) p3[i] = 0.f;
}

// ---------------- bf16 split conversions ----------------
__global__ void cvt_x_kernel(const float* __restrict__ X, int t, int M)
{
    int i = blockIdx.x * blockDim.x + threadIdx.x;
    if (i >= M * 256) return;
    int n = i >> 8, k = i & 255;
    float v = X[i];
    __nv_bfloat16 hi = __float2bfloat16(v);
    __nv_bfloat16 lo = __float2bfloat16(v - __bfloat162float(hi));
    __nv_bfloat16* d = g_xc[t] + (long long)n * 768;
    d[k] = hi; d[256 + k] = hi; d[512 + k] = lo;
}

__global__ void cvt_w_kernel(const float* __restrict__ W, int t)
{
    int i = blockIdx.x * blockDim.x + threadIdx.x;
    if (i >= 512 * 256) return;
    int n = i >> 8, k = i & 255;
    float v = W[i];
    __nv_bfloat16 hi = __float2bfloat16(v);
    __nv_bfloat16 lo = __float2bfloat16(v - __bfloat162float(hi));
    __nv_bfloat16* d = g_wc[t] + (long long)n * 768;
    d[k] = hi; d[256 + k] = lo; d[512 + k] = hi;
}

// ---------------- HMMA helpers ----------------
__device__ __forceinline__ void ldsm4(u32* r, u32 addr)
{
    asm volatile("ldmatrix.sync.aligned.m8n8.x4.shared.b16 {%0,%1,%2,%3}, [%4];"
                 : "=r"(r[0]), "=r"(r[1]), "=r"(r[2]), "=r"(r[3]) : "r"(addr));
}
__device__ __forceinline__ void mma_bf16(float* c, const u32* a, u32 b0, u32 b1)
{
    asm volatile("mma.sync.aligned.m16n8k16.row.col.f32.bf16.bf16.f32 "
                 "{%0,%1,%2,%3}, {%4,%5,%6,%7}, {%8,%9}, {%0,%1,%2,%3};"
                 : "+f"(c[0]), "+f"(c[1]), "+f"(c[2]), "+f"(c[3])
                 : "r"(a[0]), "r"(a[1]), "r"(a[2]), "r"(a[3]), "r"(b0), "r"(b1));
}

// ---------------- V projection on tensor cores ----------------
// C[M,512] = A'[M,768] @ W'[512,768]^T + bias (bf16-split, fp32 accum)
// CTA tile 128x128, 8 warps (2 m x 4 n), warp tile 64x32, K stage 32.
#define KSTRIDE 40
__global__ void __launch_bounds__(256) hgemm_kernel(int item, const float* __restrict__ bias, int M)
{
    __shared__ __nv_bfloat16 As[2][128 * KSTRIDE];
    __shared__ __nv_bfloat16 Bs[2][128 * KSTRIDE];
    const __nv_bfloat16* Ac = g_xc[item];
    const __nv_bfloat16* Wc = g_wc[item];
    float* C = g_v[item];

    int tid  = threadIdx.x;
    int lane = tid & 31, wid = tid >> 5;
    int mw = wid & 1, nw = wid >> 1;
    int mbase = blockIdx.y * 128, nbase = blockIdx.x * 128;

    int r0 = tid >> 2, ch = (tid & 3) * 8;
    int r1 = r0 + 64;
    const __nv_bfloat16* Ap0 = Ac + (long long)(mbase + r0) * 768 + ch;
    const __nv_bfloat16* Ap1 = Ac + (long long)(mbase + r1) * 768 + ch;
    const __nv_bfloat16* Bp0 = Wc + (long long)(nbase + r0) * 768 + ch;
    const __nv_bfloat16* Bp1 = Wc + (long long)(nbase + r1) * 768 + ch;
    int sA0 = r0 * KSTRIDE + ch, sA1 = r1 * KSTRIDE + ch;

    u32 smA = (u32)__cvta_generic_to_shared(&As[0][0]);
    u32 smB = (u32)__cvta_generic_to_shared(&Bs[0][0]);
    const u32 BUFB = 128 * KSTRIDE * 2;

    int arow = mw * 64 + (lane & 15);
    int acol = (lane >> 4) * 8;
    int brow = nw * 32 + (lane & 7) + ((lane >> 4) << 3);
    int bkof = lane & 8;

    float acc[4][4][4];
    #pragma unroll
    for (int i = 0; i < 4; i++)
        #pragma unroll
        for (int j = 0; j < 4; j++)
            #pragma unroll
            for (int q = 0; q < 4; q++) acc[i][j][q] = 0.f;

    float4 pa0, pa1, pb0, pb1;
    pa0 = *(const float4*)(Ap0); pa1 = *(const float4*)(Ap1);
    pb0 = *(const float4*)(Bp0); pb1 = *(const float4*)(Bp1);
    *(float4*)(&As[0][sA0]) = pa0; *(float4*)(&As[0][sA1]) = pa1;
    *(float4*)(&Bs[0][sA0]) = pb0; *(float4*)(&Bs[0][sA1]) = pb1;
    __syncthreads();

    const int NSTAGE = 24;
    for (int s = 0; s < NSTAGE; s++) {
        int buf = s & 1;
        if (s + 1 < NSTAGE) {
            int k0 = (s + 1) * 32;
            pa0 = *(const float4*)(Ap0 + k0); pa1 = *(const float4*)(Ap1 + k0);
            pb0 = *(const float4*)(Bp0 + k0); pb1 = *(const float4*)(Bp1 + k0);
        }
        u32 bA = smA + buf * BUFB;
        u32 bB = smB + buf * BUFB;
        #pragma unroll
        for (int ks = 0; ks < 32; ks += 16) {
            u32 a[4][4];
            #pragma unroll
            for (int mt = 0; mt < 4; mt++)
                ldsm4(a[mt], bA + ((arow + mt * 16) * KSTRIDE + ks + acol) * 2);
            u32 b[2][4];
            #pragma unroll
            for (int p = 0; p < 2; p++)
                ldsm4(b[p], bB + ((brow + p * 16) * KSTRIDE + ks + bkof) * 2);
            #pragma unroll
            for (int mt = 0; mt < 4; mt++)
                #pragma unroll
                for (int nt = 0; nt < 4; nt++)
                    mma_bf16(acc[mt][nt], a[mt],
                             b[nt >> 1][(nt & 1) * 2], b[nt >> 1][(nt & 1) * 2 + 1]);
        }
        if (s + 1 < NSTAGE) {
            __syncthreads();
            int nb2 = (s + 1) & 1;
            *(float4*)(&As[nb2][sA0]) = pa0; *(float4*)(&As[nb2][sA1]) = pa1;
            *(float4*)(&Bs[nb2][sA0]) = pb0; *(float4*)(&Bs[nb2][sA1]) = pb1;
            __syncthreads();
        }
    }

    int g = lane >> 2, t2 = (lane & 3) * 2;
    #pragma unroll
    for (int mt = 0; mt < 4; mt++) {
        int row = mbase + mw * 64 + mt * 16 + g;
        #pragma unroll
        for (int nt = 0; nt < 4; nt++) {
            int col = nbase + nw * 32 + nt * 8 + t2;
            float bx = bias[col], by = bias[col + 1];
            if (row < M) {
                float2 o = make_float2(acc[mt][nt][0] + bx, acc[mt][nt][1] + by);
                *(float2*)(C + (long long)row * 512 + col) = o;
            }
            if (row + 8 < M) {
                float2 o = make_float2(acc[mt][nt][2] + bx, acc[mt][nt][3] + by);
                *(float2*)(C + (long long)(row + 8) * 512 + col) = o;
            }
        }
    }
}

// ---------------- attention scalars: a[n,h] = x[n,:].weff[t,h,:] + beff ----
__global__ void __launch_bounds__(256) attn_scalar_kernel(const float* __restrict__ x_u,
        const float* __restrict__ x_i, int NUn, int NIn)
{
    int t = blockIdx.y;
    int Nn = t ? NIn : NUn;
    const float* X = t ? x_i : x_u;
    __shared__ float xs[16][260];
    __shared__ float ws[16][260];
    int tid = threadIdx.x;
    int nb = blockIdx.x * 16;
    for (int i = tid; i < 16 * 256; i += 256) {
        int r = i >> 8, c = i & 255;
        ws[r][c] = g_weff[t * 2 + (r >> 3)][(r & 7) * 256 + c];
    }
    for (int i = tid; i < 16 * 64; i += 256) {
        int r = i >> 6, c = i & 63;
        float4 v = make_float4(0.f, 0.f, 0.f, 0.f);
        if (nb + r < Nn) v = *(const float4*)(X + (long long)(nb + r) * 256 + c * 4);
        *(float4*)(&xs[r][c * 4]) = v;
    }
    __syncthreads();
    int ln = tid >> 4;
    int o  = tid & 15;
    float acc = 0.f;
    #pragma unroll 4
    for (int k = 0; k < 256; k += 4) {
        float4 xv = *(const float4*)(&xs[ln][k]);
        float4 wv = *(const float4*)(&ws[o][k]);
        acc += xv.x * wv.x + xv.y * wv.y + xv.z * wv.z + xv.w * wv.w;
    }
    int node = nb + ln;
    if (node < Nn) {
        int slice = t * 2 + (o >> 3);
        g_a[slice][node * 8 + (o & 7)] = acc + g_beff[slice][o & 7];
    }
}

// ---------------- edge pass 1: exp(score), denominators, degrees ----------
__global__ void edge1_kernel(const int* __restrict__ src, const int* __restrict__ dst,
                             int et, int sliceS, int sliceD, int E)
{
    int idx = blockIdx.x * blockDim.x + threadIdx.x;
    if (idx >= E * 8) return;
    int e = idx >> 3, h = idx & 7;
    int s = src[e], d = dst[e];
    float sc = (g_a[sliceS][s * 8 + h] + g_a[sliceD][d * 8 + h]) * 0.125f;
    float w = expf(sc);
    g_w[et][e * 8 + h] = w;
    atomicAdd(&g_den[et][d * 8 + h], w);
    if (h == 0) atomicAdd(&g_deg[et][d], 1.0f);
}

// ---------------- edge pass 2: scatter-add exp(score)*v into num ----------
__global__ void __launch_bounds__(256) edge2_kernel(const int* __restrict__ src,
        const int* __restrict__ dst, int et, int vsel, int E)
{
    int gw = (int)((blockIdx.x * blockDim.x + threadIdx.x) >> 5);
    int lane = threadIdx.x & 31;
    if (gw >= E) return;
    int s = __ldg(src + gw), d = __ldg(dst + gw);
    const float* vrow = g_v[vsel] + (long long)s * 512;
    float wv = 0.f;
    if (lane < 8) wv = g_w[et][gw * 8 + lane];
    float* nrow = g_num[et] + (long long)d * 512;
    #pragma unroll
    for (int c = 0; c < 4; c++) {
        int off = (c * 32 + lane) * 4;
        float4 v = *(const float4*)(vrow + off);
        float wh = __shfl_sync(0xffffffffu, wv, off >> 6);
        float4 m = make_float4(v.x * wh, v.y * wh, v.z * wh, v.w * wh);
        atomicAdd((float4*)(nrow + off), m);
    }
}

// ---------------- finalize: normalize + inter-type sum, write output ------
__global__ void finalize_kernel(float* __restrict__ out, int NUn, int NIn)
{
    int idx = blockIdx.x * blockDim.x + threadIdx.x;
    int totU = NUn * 128;
    int tot = totU + NIn * 128;
    if (idx >= tot) return;
    if (idx < totU) {
        int n = idx >> 7, j = idx & 127;
        int h = j >> 4;
        float4 a = *(const float4*)(g_num[1] + (long long)n * 512 + j * 4);
        float4 b = *(const float4*)(g_num[2] + (long long)n * 512 + j * 4);
        float den1 = g_den[1][n * 8 + h], den2 = g_den[2][n * 8 + h];
        float s1 = den1 > 0.f ? 1.f / (den1 * g_deg[1][n]) : 0.f;
        float s2 = den2 > 0.f ? 1.f / (den2 * g_deg[2][n]) : 0.f;
        float4 r = make_float4(a.x * s1 + b.x * s2, a.y * s1 + b.y * s2,
                               a.z * s1 + b.z * s2, a.w * s1 + b.w * s2);
        *(float4*)(out + (long long)n * 512 + j * 4) = r;
    } else {
        int m = idx - totU;
        int n = m >> 7, j = m & 127;
        int h = j >> 4;
        float4 a = *(const float4*)(g_num[0] + (long long)n * 512 + j * 4);
        float den0 = g_den[0][n * 8 + h];
        float s0 = den0 > 0.f ? 1.f / (den0 * g_deg[0][n]) : 0.f;
        float4 r = make_float4(a.x * s0, a.y * s0, a.z * s0, a.w * s0);
        *(float4*)(out + (long long)NUn * 512 + (long long)n * 512 + j * 4) = r;
    }
}

// ---------------- launch ----------------
extern "C" void kernel_launch(void* const* d_in, const int* in_sizes, int n_in,
                              void* d_out, int out_size)
{
    const float* x_u  = (const float*)d_in[0];
    const float* x_i  = (const float*)d_in[1];
    const float* Wq_u = (const float*)d_in[2];  const float* bq_u = (const float*)d_in[3];
    const float* Wk_u = (const float*)d_in[4];  const float* bk_u = (const float*)d_in[5];
    const float* Wv_u = (const float*)d_in[6];  const float* bv_u = (const float*)d_in[7];
    const float* Wq_i = (const float*)d_in[8];  const float* bq_i = (const float*)d_in[9];
    const float* Wk_i = (const float*)d_in[10]; const float* bk_i = (const float*)d_in[11];
    const float* Wv_i = (const float*)d_in[12]; const float* bv_i = (const float*)d_in[13];
    const float* wa_u = (const float*)d_in[14];
    const float* wa_i = (const float*)d_in[15];
    const int* src_c  = (const int*)d_in[16];   const int* dst_c  = (const int*)d_in[17];
    const int* src_cb = (const int*)d_in[18];   const int* dst_cb = (const int*)d_in[19];
    const int* src_f  = (const int*)d_in[20];   const int* dst_f  = (const int*)d_in[21];
    int NUn = in_sizes[0] / 256;
    int NIn = in_sizes[1] / 256;
    int E0 = in_sizes[16], E1 = in_sizes[18], E2 = in_sizes[20];
    float* out = (float*)d_out;

    weff_kernel<<<33, 256>>>(Wq_u, Wk_u, Wq_i, Wk_i, bq_u, bk_u, bq_i, bk_i, wa_u, wa_i);
    zero_kernel<<<2048, 256>>>();
    cvt_w_kernel<<<512, 256>>>(Wv_u, 0);
    cvt_w_kernel<<<512, 256>>>(Wv_i, 1);
    cvt_x_kernel<<<(NUn * 256 + 255) / 256, 256>>>(x_u, 0, NUn);
    cvt_x_kernel<<<(NIn * 256 + 255) / 256, 256>>>(x_i, 1, NIn);
    hgemm_kernel<<<dim3(4, (NUn + 127) / 128), 256>>>(0, bv_u, NUn);
    hgemm_kernel<<<dim3(4, (NIn + 127) / 128), 256>>>(1, bv_i, NIn);
    int NMaxN = NUn > NIn ? NUn : NIn;
    attn_scalar_kernel<<<dim3((NMaxN + 15) / 16, 2), 256>>>(x_u, x_i, NUn, NIn);
    edge1_kernel<<<(E0 * 8 + 255) / 256, 256>>>(src_c, dst_c, 0, 1, 2, E0);
    edge1_kernel<<<(E1 * 8 + 255) / 256, 256>>>(src_cb, dst_cb, 1, 3, 0, E1);
    edge1_kernel<<<(E2 * 8 + 255) / 256, 256>>>(src_f, dst_f, 2, 1, 0, E2);
    edge2_kernel<<<(E0 * 32 + 255) / 256, 256>>>(src_c, dst_c, 0, 0, E0);
    edge2_kernel<<<(E1 * 32 + 255) / 256, 256>>>(src_cb, dst_cb, 1, 1, E1);
    edge2_kernel<<<(E2 * 32 + 255) / 256, 256>>>(src_f, dst_f, 2, 0, E2);
    finalize_kernel<<<((NUn + NIn) * 128 + 255) / 256, 256>>>(out, NUn, NIn);
}

// round 11
// speedup vs baseline: 1.7355x; 1.2718x over previous
#include <cuda_runtime.h>
#include <cuda_bf16.h>
#include <cstdint>

typedef unsigned int u32;

#define NMAX 50000
#define EMAX 100000
#define WCSZ 262144     /* 512 * 512 : [hi(256)|lo(256)] per row */

// ---------------- device scratch (static allocation, allowed) ----------------
__device__ float g_v[2][NMAX * 512];      // v_user, v_item
__device__ float g_a[4][NMAX * 8];        // aq_u, ak_u, aq_i, ak_i
__device__ float g_weff[4][8 * 256];      // effective attn-scalar weights
__device__ float g_beff[4][8];            // effective attn-scalar biases
__device__ float g_den[3][NMAX * 8];      // per-etype softmax denominators
__device__ float g_deg[3][NMAX];          // per-etype in-degree
__device__ float g_w[3][EMAX * 8];        // per-edge exp(score) per head
__device__ __nv_bfloat16 g_wc[2][WCSZ];   // W split: [hi | lo] per row

// ---------------- effective weights: weff[t][h][k] = sum_d W[h*64+d][k]*wa[d]
__global__ void weff_kernel(const float* __restrict__ Wq_u, const float* __restrict__ Wk_u,
                            const float* __restrict__ Wq_i, const float* __restrict__ Wk_i,
                            const float* __restrict__ bq_u, const float* __restrict__ bk_u,
                            const float* __restrict__ bq_i, const float* __restrict__ bk_i,
                            const float* __restrict__ wa_u, const float* __restrict__ wa_i)
{
    int b = blockIdx.x;
    if (b < 32) {
        int t = b >> 3, h = b & 7;
        const float* W  = (t == 0) ? Wq_u : (t == 1) ? Wk_u : (t == 2) ? Wq_i : Wk_i;
        const float* wa = (t < 2) ? wa_u : wa_i;
        __shared__ float was[64];
        if (threadIdx.x < 64) was[threadIdx.x] = wa[threadIdx.x];
        __syncthreads();
        int k = threadIdx.x;
        float acc = 0.f;
        #pragma unroll 8
        for (int d = 0; d < 64; d++)
            acc += W[(h * 64 + d) * 256 + k] * was[d];
        g_weff[t][h * 256 + k] = acc;
    } else {
        if (threadIdx.x < 32) {
            int t = threadIdx.x >> 3, h = threadIdx.x & 7;
            const float* bb = (t == 0) ? bq_u : (t == 1) ? bk_u : (t == 2) ? bq_i : bk_i;
            const float* wa = (t < 2) ? wa_u : wa_i;
            float acc = 0.f;
            for (int d = 0; d < 64; d++) acc += bb[h * 64 + d] * wa[d];
            g_beff[t][h] = acc;
        }
    }
}

// ---------------- zero: output buffer + den + deg ----------------
__global__ void zero_kernel(float* __restrict__ out, long long outN)
{
    long long idx = (long long)blockIdx.x * blockDim.x + threadIdx.x;
    long long stride = (long long)gridDim.x * blockDim.x;
    float4 z = make_float4(0.f, 0.f, 0.f, 0.f);
    float4* p = (float4*)out;
    long long n = outN / 4;
    for (long long i = idx; i < n; i += stride) p[i] = z;
    float4* p2 = (float4*)&g_den[0][0];
    long long n2 = (long long)3 * NMAX * 8 / 4;
    for (long long i = idx; i < n2; i += stride) p2[i] = z;
    float* p3 = &g_deg[0][0];
    long long n3 = (long long)3 * NMAX;
    for (long long i = idx; i < n3; i += stride) p3[i] = 0.f;
}

// ---------------- W bf16 split: [hi | lo] ----------------
__global__ void cvt_w_kernel(const float* __restrict__ W, int t)
{
    int i = blockIdx.x * blockDim.x + threadIdx.x;
    if (i >= 512 * 256) return;
    int n = i >> 8, k = i & 255;
    float v = W[i];
    __nv_bfloat16 hi = __float2bfloat16(v);
    __nv_bfloat16 lo = __float2bfloat16(v - __bfloat162float(hi));
    __nv_bfloat16* d = g_wc[t] + n * 512;
    d[k] = hi; d[256 + k] = lo;
}

// ---------------- HMMA helpers ----------------
__device__ __forceinline__ void ldsm4(u32* r, u32 addr)
{
    asm volatile("ldmatrix.sync.aligned.m8n8.x4.shared.b16 {%0,%1,%2,%3}, [%4];"
                 : "=r"(r[0]), "=r"(r[1]), "=r"(r[2]), "=r"(r[3]) : "r"(addr));
}
__device__ __forceinline__ void mma_bf16(float* c, const u32* a, u32 b0, u32 b1)
{
    asm volatile("mma.sync.aligned.m16n8k16.row.col.f32.bf16.bf16.f32 "
                 "{%0,%1,%2,%3}, {%4,%5,%6,%7}, {%8,%9}, {%0,%1,%2,%3};"
                 : "+f"(c[0]), "+f"(c[1]), "+f"(c[2]), "+f"(c[3])
                 : "r"(a[0]), "r"(a[1]), "r"(a[2]), "r"(a[3]), "r"(b0), "r"(b1));
}

// ---------------- fused split + V projection on tensor cores ----------------
// C[M,512] = X[M,256] @ W[512,256]^T + bias, bf16-split (hh + hl + lh), fp32 acc
// CTA 128x128, 8 warps (2m x 4n), warp 64x32, K stage 32, 8 stages.
// Static smem: 4 tiles (Ahi,Alo,Bhi,Blo) x 128 x KSTRIDE bf16 = 40960 B,
// single-buffered; next stage is held in registers during compute.
#define KSTRIDE 40
#define TILESZ (128 * KSTRIDE)
__global__ void __launch_bounds__(256) hgemm2_kernel(const float* __restrict__ X,
        int item, const float* __restrict__ bias, int M)
{
    __shared__ __nv_bfloat16 sm[4 * TILESZ];
    const __nv_bfloat16* Wc = g_wc[item];
    float* C = g_v[item];

    int tid  = threadIdx.x;
    int lane = tid & 31, wid = tid >> 5;
    int mw = wid & 1, nw = wid >> 1;
    int mbase = blockIdx.y * 128, nbase = blockIdx.x * 128;

    // load mapping: row = tid>>1 (0..127), colbase = (tid&1)*16
    int lrow = tid >> 1, cb = (tid & 1) * 16;
    int avalid = (mbase + lrow) < M;
    const float* Ap = X + (long long)(mbase + lrow) * 256 + cb;
    const __nv_bfloat16* Bph = Wc + (nbase + lrow) * 512 + cb;
    const __nv_bfloat16* Bpl = Bph + 256;
    int sOff = lrow * KSTRIDE + cb;

    u32 smBase = (u32)__cvta_generic_to_shared(sm);
    const u32 TB = TILESZ * 2;                 // tile bytes
    u32 bAh = smBase;
    u32 bAl = bAh + TB;
    u32 bBh = bAl + TB;
    u32 bBl = bBh + TB;

    int arow = mw * 64 + (lane & 15);
    int acol = (lane >> 4) * 8;
    int brow = nw * 32 + (lane & 7) + ((lane >> 4) << 3);
    int bkof = lane & 8;

    float acc[4][4][4];
    #pragma unroll
    for (int i = 0; i < 4; i++)
        #pragma unroll
        for (int j = 0; j < 4; j++)
            #pragma unroll
            for (int q = 0; q < 4; q++) acc[i][j][q] = 0.f;

    float4 pa[4];
    float4 pbh[2], pbl[2];

    // store current regs (one 128x32 stage of A split + B hi/lo) into smem
    #define STORE_STAGE()                                                        \
    {                                                                            \
        __nv_bfloat16* Ah = sm;                                                  \
        __nv_bfloat16* Al = Ah + TILESZ;                                         \
        __nv_bfloat16* Bh = Al + TILESZ;                                         \
        __nv_bfloat16* Bl = Bh + TILESZ;                                         \
        _Pragma("unroll")                                                        \
        for (int j = 0; j < 4; j++) {                                            \
            float4 v = pa[j];                                                    \
            __nv_bfloat16 hx = __float2bfloat16(v.x);                            \
            __nv_bfloat16 hy = __float2bfloat16(v.y);                            \
            __nv_bfloat16 hz = __float2bfloat16(v.z);                            \
            __nv_bfloat16 hw = __float2bfloat16(v.w);                            \
            __nv_bfloat162 h01, h23, l01, l23;                                   \
            h01.x = hx; h01.y = hy; h23.x = hz; h23.y = hw;                      \
            l01.x = __float2bfloat16(v.x - __bfloat162float(hx));                \
            l01.y = __float2bfloat16(v.y - __bfloat162float(hy));                \
            l23.x = __float2bfloat16(v.z - __bfloat162float(hz));                \
            l23.y = __float2bfloat16(v.w - __bfloat162float(hw));                \
            *(__nv_bfloat162*)(Ah + sOff + j * 4)     = h01;                     \
            *(__nv_bfloat162*)(Ah + sOff + j * 4 + 2) = h23;                     \
            *(__nv_bfloat162*)(Al + sOff + j * 4)     = l01;                     \
            *(__nv_bfloat162*)(Al + sOff + j * 4 + 2) = l23;                     \
        }                                                                        \
        *(float4*)(Bh + sOff)     = pbh[0];                                      \
        *(float4*)(Bh + sOff + 8) = pbh[1];                                      \
        *(float4*)(Bl + sOff)     = pbl[0];                                      \
        *(float4*)(Bl + sOff + 8) = pbl[1];                                      \
    }

    // preload stage 0 into regs, store to smem
    {
        #pragma unroll
        for (int j = 0; j < 4; j++)
            pa[j] = avalid ? *(const float4*)(Ap + j * 4)
                           : make_float4(0.f, 0.f, 0.f, 0.f);
        pbh[0] = *(const float4*)(Bph);     pbh[1] = *(const float4*)(Bph + 8);
        pbl[0] = *(const float4*)(Bpl);     pbl[1] = *(const float4*)(Bpl + 8);
        STORE_STAGE()
    }
    __syncthreads();

    const int NSTAGE = 8;                       // 256 / 32
    for (int s = 0; s < NSTAGE; s++) {
        if (s + 1 < NSTAGE) {
            int k0 = (s + 1) * 32;
            #pragma unroll
            for (int j = 0; j < 4; j++)
                pa[j] = avalid ? *(const float4*)(Ap + k0 + j * 4)
                               : make_float4(0.f, 0.f, 0.f, 0.f);
            pbh[0] = *(const float4*)(Bph + k0);     pbh[1] = *(const float4*)(Bph + k0 + 8);
            pbl[0] = *(const float4*)(Bpl + k0);     pbl[1] = *(const float4*)(Bpl + k0 + 8);
        }
        #pragma unroll
        for (int ks = 0; ks < 32; ks += 16) {
            u32 ah[4][4], al[4][4];
            #pragma unroll
            for (int mt = 0; mt < 4; mt++) {
                u32 ro = ((arow + mt * 16) * KSTRIDE + ks + acol) * 2;
                ldsm4(ah[mt], bAh + ro);
                ldsm4(al[mt], bAl + ro);
            }
            u32 bh[2][4], bl[2][4];
            #pragma unroll
            for (int p = 0; p < 2; p++) {
                u32 ro = ((brow + p * 16) * KSTRIDE + ks + bkof) * 2;
                ldsm4(bh[p], bBh + ro);
                ldsm4(bl[p], bBl + ro);
            }
            #pragma unroll
            for (int mt = 0; mt < 4; mt++)
                #pragma unroll
                for (int nt = 0; nt < 4; nt++) {
                    u32 h0 = bh[nt >> 1][(nt & 1) * 2], h1 = bh[nt >> 1][(nt & 1) * 2 + 1];
                    u32 l0 = bl[nt >> 1][(nt & 1) * 2], l1 = bl[nt >> 1][(nt & 1) * 2 + 1];
                    mma_bf16(acc[mt][nt], ah[mt], h0, h1);   // hi*hi
                    mma_bf16(acc[mt][nt], ah[mt], l0, l1);   // hi*lo
                    mma_bf16(acc[mt][nt], al[mt], h0, h1);   // lo*hi
                }
        }
        if (s + 1 < NSTAGE) {
            __syncthreads();
            STORE_STAGE()
            __syncthreads();
        }
    }

    int g = lane >> 2, t2 = (lane & 3) * 2;
    #pragma unroll
    for (int mt = 0; mt < 4; mt++) {
        int row = mbase + mw * 64 + mt * 16 + g;
        #pragma unroll
        for (int nt = 0; nt < 4; nt++) {
            int col = nbase + nw * 32 + nt * 8 + t2;
            float bx = bias[col], by = bias[col + 1];
            if (row < M) {
                float2 o = make_float2(acc[mt][nt][0] + bx, acc[mt][nt][1] + by);
                *(float2*)(C + (long long)row * 512 + col) = o;
            }
            if (row + 8 < M) {
                float2 o = make_float2(acc[mt][nt][2] + bx, acc[mt][nt][3] + by);
                *(float2*)(C + (long long)(row + 8) * 512 + col) = o;
            }
        }
    }
    #undef STORE_STAGE
}

// ---------------- attention scalars: a[n,h] = x[n,:].weff[t,h,:] + beff ----
__global__ void __launch_bounds__(256) attn_scalar_kernel(const float* __restrict__ x_u,
        const float* __restrict__ x_i, int NUn, int NIn)
{
    int t = blockIdx.y;
    int Nn = t ? NIn : NUn;
    const float* X = t ? x_i : x_u;
    __shared__ float xs[16][260];
    __shared__ float ws[16][260];
    int tid = threadIdx.x;
    int nb = blockIdx.x * 16;
    for (int i = tid; i < 16 * 256; i += 256) {
        int r = i >> 8, c = i & 255;
        ws[r][c] = g_weff[t * 2 + (r >> 3)][(r & 7) * 256 + c];
    }
    for (int i = tid; i < 16 * 64; i += 256) {
        int r = i >> 6, c = i & 63;
        float4 v = make_float4(0.f, 0.f, 0.f, 0.f);
        if (nb + r < Nn) v = *(const float4*)(X + (long long)(nb + r) * 256 + c * 4);
        *(float4*)(&xs[r][c * 4]) = v;
    }
    __syncthreads();
    int ln = tid >> 4;
    int o  = tid & 15;
    float acc = 0.f;
    #pragma unroll 4
    for (int k = 0; k < 256; k += 4) {
        float4 xv = *(const float4*)(&xs[ln][k]);
        float4 wv = *(const float4*)(&ws[o][k]);
        acc += xv.x * wv.x + xv.y * wv.y + xv.z * wv.z + xv.w * wv.w;
    }
    int node = nb + ln;
    if (node < Nn) {
        int slice = t * 2 + (o >> 3);
        g_a[slice][node * 8 + (o & 7)] = acc + g_beff[slice][o & 7];
    }
}

// ---------------- edge pass 1: exp(score), denominators, degrees ----------
__global__ void edge1_kernel(const int* __restrict__ src, const int* __restrict__ dst,
                             int et, int sliceS, int sliceD, int E)
{
    int idx = blockIdx.x * blockDim.x + threadIdx.x;
    if (idx >= E * 8) return;
    int e = idx >> 3, h = idx & 7;
    int s = src[e], d = dst[e];
    float sc = (g_a[sliceS][s * 8 + h] + g_a[sliceD][d * 8 + h]) * 0.125f;
    float w = expf(sc);
    g_w[et][e * 8 + h] = w;
    atomicAdd(&g_den[et][d * 8 + h], w);
    if (h == 0) atomicAdd(&g_deg[et][d], 1.0f);
}

// ---------------- edge pass 2: normalized scatter-add directly into out ----
// warp per edge; weight w/(den*deg); float4 atomics into output region
__global__ void __launch_bounds__(256) edge2_kernel(const int* __restrict__ src,
        const int* __restrict__ dst, int et, int vsel, float* __restrict__ outBase, int E)
{
    int gw = (int)((blockIdx.x * blockDim.x + threadIdx.x) >> 5);
    int lane = threadIdx.x & 31;
    if (gw >= E) return;
    int s = __ldg(src + gw), d = __ldg(dst + gw);
    const float* vrow = g_v[vsel] + (long long)s * 512;
    float wv = 0.f;
    if (lane < 8) {
        float den = g_den[et][d * 8 + lane];
        float dg  = g_deg[et][d];
        wv = g_w[et][gw * 8 + lane] / (den * dg);
    }
    float* nrow = outBase + (long long)d * 512;
    #pragma unroll
    for (int c = 0; c < 4; c++) {
        int off = (c * 32 + lane) * 4;
        float4 v = *(const float4*)(vrow + off);
        float wh = __shfl_sync(0xffffffffu, wv, off >> 6);
        float4 m = make_float4(v.x * wh, v.y * wh, v.z * wh, v.w * wh);
        atomicAdd((float4*)(nrow + off), m);
    }
}

// ---------------- launch ----------------
extern "C" void kernel_launch(void* const* d_in, const int* in_sizes, int n_in,
                              void* d_out, int out_size)
{
    const float* x_u  = (const float*)d_in[0];
    const float* x_i  = (const float*)d_in[1];
    const float* Wq_u = (const float*)d_in[2];  const float* bq_u = (const float*)d_in[3];
    const float* Wk_u = (const float*)d_in[4];  const float* bk_u = (const float*)d_in[5];
    const float* Wv_u = (const float*)d_in[6];  const float* bv_u = (const float*)d_in[7];
    const float* Wq_i = (const float*)d_in[8];  const float* bq_i = (const float*)d_in[9];
    const float* Wk_i = (const float*)d_in[10]; const float* bk_i = (const float*)d_in[11];
    const float* Wv_i = (const float*)d_in[12]; const float* bv_i = (const float*)d_in[13];
    const float* wa_u = (const float*)d_in[14];
    const float* wa_i = (const float*)d_in[15];
    const int* src_c  = (const int*)d_in[16];   const int* dst_c  = (const int*)d_in[17];
    const int* src_cb = (const int*)d_in[18];   const int* dst_cb = (const int*)d_in[19];
    const int* src_f  = (const int*)d_in[20];   const int* dst_f  = (const int*)d_in[21];
    int NUn = in_sizes[0] / 256;
    int NIn = in_sizes[1] / 256;
    int E0 = in_sizes[16], E1 = in_sizes[18], E2 = in_sizes[20];
    float* out = (float*)d_out;

    weff_kernel<<<33, 256>>>(Wq_u, Wk_u, Wq_i, Wk_i, bq_u, bk_u, bq_i, bk_i, wa_u, wa_i);
    zero_kernel<<<2048, 256>>>(out, (long long)(NUn + NIn) * 512);
    cvt_w_kernel<<<512, 256>>>(Wv_u, 0);
    cvt_w_kernel<<<512, 256>>>(Wv_i, 1);
    hgemm2_kernel<<<dim3(4, (NUn + 127) / 128), 256>>>(x_u, 0, bv_u, NUn);
    hgemm2_kernel<<<dim3(4, (NIn + 127) / 128), 256>>>(x_i, 1, bv_i, NIn);
    int NMaxN = NUn > NIn ? NUn : NIn;
    attn_scalar_kernel<<<dim3((NMaxN + 15) / 16, 2), 256>>>(x_u, x_i, NUn, NIn);
    edge1_kernel<<<(E0 * 8 + 255) / 256, 256>>>(src_c, dst_c, 0, 1, 2, E0);
    edge1_kernel<<<(E1 * 8 + 255) / 256, 256>>>(src_cb, dst_cb, 1, 3, 0, E1);
    edge1_kernel<<<(E2 * 8 + 255) / 256, 256>>>(src_f, dst_f, 2, 1, 0, E2);
    // etype0: dst=item -> item region; etype1,2: dst=user -> user region
    edge2_kernel<<<(E0 * 32 + 255) / 256, 256>>>(src_c, dst_c, 0, 0,
                                                 out + (long long)NUn * 512, E0);
    edge2_kernel<<<(E1 * 32 + 255) / 256, 256>>>(src_cb, dst_cb, 1, 1, out, E1);
    edge2_kernel<<<(E2 * 32 + 255) / 256, 256>>>(src_f, dst_f, 2, 0, out, E2);
}

// round 13
// speedup vs baseline: 1.8153x; 1.0459x over previous
#include <cuda_runtime.h>
#include <cuda_bf16.h>
#include <cstdint>

typedef unsigned int u32;

#define NMAX 50000
#define EMAX 100000
#define WCSZ 262144     /* 512 * 512 : [hi(256)|lo(256)] per row */

// ---------------- device scratch (static allocation, allowed) ----------------
__device__ float g_v[2][NMAX * 512];      // v_user, v_item
__device__ float g_a[4][NMAX * 8];        // aq_u, ak_u, aq_i, ak_i
__device__ float g_weff[4][8 * 256];      // effective attn-scalar weights
__device__ float g_beff[4][8];            // effective attn-scalar biases
__device__ float g_den[3][NMAX * 8];      // per-etype softmax denominators
__device__ float g_deg[3][NMAX];          // per-etype in-degree
__device__ float g_w[3][EMAX * 8];        // per-edge exp(score) per head
__device__ __nv_bfloat16 g_wc[2][WCSZ];   // W split: [hi | lo] per row

// ---------------- prep: zero(out,den,deg) + cvt_w(x2) + weff, one launch ----
// block map: [0,1024) cvt_w, [1024,1057) weff, [1057,...) zero (grid-stride)
__global__ void prep_kernel(float* __restrict__ out, long long outN,
                            const float* __restrict__ Wv_u, const float* __restrict__ Wv_i,
                            const float* __restrict__ Wq_u, const float* __restrict__ Wk_u,
                            const float* __restrict__ Wq_i, const float* __restrict__ Wk_i,
                            const float* __restrict__ bq_u, const float* __restrict__ bk_u,
                            const float* __restrict__ bq_i, const float* __restrict__ bk_i,
                            const float* __restrict__ wa_u, const float* __restrict__ wa_i)
{
    int b = blockIdx.x;
    if (b < 1024) {
        // W bf16 split: [hi | lo], 512 blocks per weight tensor
        int t = b >> 9;
        int i = (b & 511) * 256 + threadIdx.x;      // 0 .. 131071
        const float* W = t ? Wv_i : Wv_u;
        int n = i >> 8, k = i & 255;
        float v = W[i];
        __nv_bfloat16 hi = __float2bfloat16(v);
        __nv_bfloat16 lo = __float2bfloat16(v - __bfloat162float(hi));
        __nv_bfloat16* d = g_wc[t] + n * 512;
        d[k] = hi; d[256 + k] = lo;
    } else if (b < 1057) {
        int bb = b - 1024;
        if (bb < 32) {
            int t = bb >> 3, h = bb & 7;
            const float* W  = (t == 0) ? Wq_u : (t == 1) ? Wk_u : (t == 2) ? Wq_i : Wk_i;
            const float* wa = (t < 2) ? wa_u : wa_i;
            __shared__ float was[64];
            if (threadIdx.x < 64) was[threadIdx.x] = wa[threadIdx.x];
            __syncthreads();
            int k = threadIdx.x;
            float acc = 0.f;
            #pragma unroll 8
            for (int d2 = 0; d2 < 64; d2++)
                acc += W[(h * 64 + d2) * 256 + k] * was[d2];
            g_weff[t][h * 256 + k] = acc;
        } else {
            if (threadIdx.x < 32) {
                int t = threadIdx.x >> 3, h = threadIdx.x & 7;
                const float* bb2 = (t == 0) ? bq_u : (t == 1) ? bk_u : (t == 2) ? bq_i : bk_i;
                const float* wa = (t < 2) ? wa_u : wa_i;
                float acc = 0.f;
                for (int d2 = 0; d2 < 64; d2++) acc += bb2[h * 64 + d2] * wa[d2];
                g_beff[t][h] = acc;
            }
        }
    } else {
        long long idx = (long long)(b - 1057) * blockDim.x + threadIdx.x;
        long long stride = (long long)(gridDim.x - 1057) * blockDim.x;
        float4 z = make_float4(0.f, 0.f, 0.f, 0.f);
        float4* p = (float4*)out;
        long long n = outN / 4;
        for (long long i = idx; i < n; i += stride) p[i] = z;
        float4* p2 = (float4*)&g_den[0][0];
        long long n2 = (long long)3 * NMAX * 8 / 4;
        for (long long i = idx; i < n2; i += stride) p2[i] = z;
        float* p3 = &g_deg[0][0];
        long long n3 = (long long)3 * NMAX;
        for (long long i = idx; i < n3; i += stride) p3[i] = 0.f;
    }
}

// ---------------- HMMA helpers ----------------
__device__ __forceinline__ void ldsm4(u32* r, u32 addr)
{
    asm volatile("ldmatrix.sync.aligned.m8n8.x4.shared.b16 {%0,%1,%2,%3}, [%4];"
                 : "=r"(r[0]), "=r"(r[1]), "=r"(r[2]), "=r"(r[3]) : "r"(addr));
}
__device__ __forceinline__ void mma_bf16(float* c, const u32* a, u32 b0, u32 b1)
{
    asm volatile("mma.sync.aligned.m16n8k16.row.col.f32.bf16.bf16.f32 "
                 "{%0,%1,%2,%3}, {%4,%5,%6,%7}, {%8,%9}, {%0,%1,%2,%3};"
                 : "+f"(c[0]), "+f"(c[1]), "+f"(c[2]), "+f"(c[3])
                 : "r"(a[0]), "r"(a[1]), "r"(a[2]), "r"(a[3]), "r"(b0), "r"(b1));
}

// ---------------- fused split + V projection on tensor cores ----------------
// Both projections in ONE launch: blockIdx.z = item (0=user, 1=item).
// C[M,512] = X[M,256] @ W[512,256]^T + bias, bf16-split (hh + hl + lh), fp32 acc
// CTA 128x128, 8 warps (2m x 4n), warp 64x32, K stage 32, 8 stages.
// Static smem 40960 B, single-buffered; next stage held in registers.
#define KSTRIDE 40
#define TILESZ (128 * KSTRIDE)
__global__ void __launch_bounds__(256) hgemm2_kernel(
        const float* __restrict__ Xu, const float* __restrict__ Xi,
        const float* __restrict__ bias_u, const float* __restrict__ bias_i,
        int Mu, int Mi)
{
    __shared__ __nv_bfloat16 sm[4 * TILESZ];
    int item = blockIdx.z;
    const float* X = item ? Xi : Xu;
    const float* bias = item ? bias_i : bias_u;
    int M = item ? Mi : Mu;
    int mbase = blockIdx.y * 128, nbase = blockIdx.x * 128;
    if (mbase >= M) return;
    const __nv_bfloat16* Wc = g_wc[item];
    float* C = g_v[item];

    int tid  = threadIdx.x;
    int lane = tid & 31, wid = tid >> 5;
    int mw = wid & 1, nw = wid >> 1;

    int lrow = tid >> 1, cb = (tid & 1) * 16;
    int avalid = (mbase + lrow) < M;
    const float* Ap = X + (long long)(mbase + lrow) * 256 + cb;
    const __nv_bfloat16* Bph = Wc + (nbase + lrow) * 512 + cb;
    const __nv_bfloat16* Bpl = Bph + 256;
    int sOff = lrow * KSTRIDE + cb;

    u32 smBase = (u32)__cvta_generic_to_shared(sm);
    const u32 TB = TILESZ * 2;
    u32 bAh = smBase;
    u32 bAl = bAh + TB;
    u32 bBh = bAl + TB;
    u32 bBl = bBh + TB;

    int arow = mw * 64 + (lane & 15);
    int acol = (lane >> 4) * 8;
    int brow = nw * 32 + (lane & 7) + ((lane >> 4) << 3);
    int bkof = lane & 8;

    float acc[4][4][4];
    #pragma unroll
    for (int i = 0; i < 4; i++)
        #pragma unroll
        for (int j = 0; j < 4; j++)
            #pragma unroll
            for (int q = 0; q < 4; q++) acc[i][j][q] = 0.f;

    float4 pa[4];
    float4 pbh[2], pbl[2];

    #define STORE_STAGE()                                                        \
    {                                                                            \
        __nv_bfloat16* Ah = sm;                                                  \
        __nv_bfloat16* Al = Ah + TILESZ;                                         \
        __nv_bfloat16* Bh = Al + TILESZ;                                         \
        __nv_bfloat16* Bl = Bh + TILESZ;                                         \
        _Pragma("unroll")                                                        \
        for (int j = 0; j < 4; j++) {                                            \
            float4 v = pa[j];                                                    \
            __nv_bfloat16 hx = __float2bfloat16(v.x);                            \
            __nv_bfloat16 hy = __float2bfloat16(v.y);                            \
            __nv_bfloat16 hz = __float2bfloat16(v.z);                            \
            __nv_bfloat16 hw = __float2bfloat16(v.w);                            \
            __nv_bfloat162 h01, h23, l01, l23;                                   \
            h01.x = hx; h01.y = hy; h23.x = hz; h23.y = hw;                      \
            l01.x = __float2bfloat16(v.x - __bfloat162float(hx));                \
            l01.y = __float2bfloat16(v.y - __bfloat162float(hy));                \
            l23.x = __float2bfloat16(v.z - __bfloat162float(hz));                \
            l23.y = __float2bfloat16(v.w - __bfloat162float(hw));                \
            *(__nv_bfloat162*)(Ah + sOff + j * 4)     = h01;                     \
            *(__nv_bfloat162*)(Ah + sOff + j * 4 + 2) = h23;                     \
            *(__nv_bfloat162*)(Al + sOff + j * 4)     = l01;                     \
            *(__nv_bfloat162*)(Al + sOff + j * 4 + 2) = l23;                     \
        }                                                                        \
        *(float4*)(Bh + sOff)     = pbh[0];                                      \
        *(float4*)(Bh + sOff + 8) = pbh[1];                                      \
        *(float4*)(Bl + sOff)     = pbl[0];                                      \
        *(float4*)(Bl + sOff + 8) = pbl[1];                                      \
    }

    {
        #pragma unroll
        for (int j = 0; j < 4; j++)
            pa[j] = avalid ? *(const float4*)(Ap + j * 4)
                           : make_float4(0.f, 0.f, 0.f, 0.f);
        pbh[0] = *(const float4*)(Bph);     pbh[1] = *(const float4*)(Bph + 8);
        pbl[0] = *(const float4*)(Bpl);     pbl[1] = *(const float4*)(Bpl + 8);
        STORE_STAGE()
    }
    __syncthreads();

    const int NSTAGE = 8;
    for (int s = 0; s < NSTAGE; s++) {
        if (s + 1 < NSTAGE) {
            int k0 = (s + 1) * 32;
            #pragma unroll
            for (int j = 0; j < 4; j++)
                pa[j] = avalid ? *(const float4*)(Ap + k0 + j * 4)
                               : make_float4(0.f, 0.f, 0.f, 0.f);
            pbh[0] = *(const float4*)(Bph + k0);     pbh[1] = *(const float4*)(Bph + k0 + 8);
            pbl[0] = *(const float4*)(Bpl + k0);     pbl[1] = *(const float4*)(Bpl + k0 + 8);
        }
        #pragma unroll
        for (int ks = 0; ks < 32; ks += 16) {
            u32 ah[4][4], al[4][4];
            #pragma unroll
            for (int mt = 0; mt < 4; mt++) {
                u32 ro = ((arow + mt * 16) * KSTRIDE + ks + acol) * 2;
                ldsm4(ah[mt], bAh + ro);
                ldsm4(al[mt], bAl + ro);
            }
            u32 bh[2][4], bl[2][4];
            #pragma unroll
            for (int p = 0; p < 2; p++) {
                u32 ro = ((brow + p * 16) * KSTRIDE + ks + bkof) * 2;
                ldsm4(bh[p], bBh + ro);
                ldsm4(bl[p], bBl + ro);
            }
            #pragma unroll
            for (int mt = 0; mt < 4; mt++)
                #pragma unroll
                for (int nt = 0; nt < 4; nt++) {
                    u32 h0 = bh[nt >> 1][(nt & 1) * 2], h1 = bh[nt >> 1][(nt & 1) * 2 + 1];
                    u32 l0 = bl[nt >> 1][(nt & 1) * 2], l1 = bl[nt >> 1][(nt & 1) * 2 + 1];
                    mma_bf16(acc[mt][nt], ah[mt], h0, h1);   // hi*hi
                    mma_bf16(acc[mt][nt], ah[mt], l0, l1);   // hi*lo
                    mma_bf16(acc[mt][nt], al[mt], h0, h1);   // lo*hi
                }
        }
        if (s + 1 < NSTAGE) {
            __syncthreads();
            STORE_STAGE()
            __syncthreads();
        }
    }

    int g = lane >> 2, t2 = (lane & 3) * 2;
    #pragma unroll
    for (int mt = 0; mt < 4; mt++) {
        int row = mbase + mw * 64 + mt * 16 + g;
        #pragma unroll
        for (int nt = 0; nt < 4; nt++) {
            int col = nbase + nw * 32 + nt * 8 + t2;
            float bx = bias[col], by = bias[col + 1];
            if (row < M) {
                float2 o = make_float2(acc[mt][nt][0] + bx, acc[mt][nt][1] + by);
                *(float2*)(C + (long long)row * 512 + col) = o;
            }
            if (row + 8 < M) {
                float2 o = make_float2(acc[mt][nt][2] + bx, acc[mt][nt][3] + by);
                *(float2*)(C + (long long)(row + 8) * 512 + col) = o;
            }
        }
    }
    #undef STORE_STAGE
}

// ---------------- attention scalars: a[n,h] = x[n,:].weff[t,h,:] + beff ----
__global__ void __launch_bounds__(256) attn_scalar_kernel(const float* __restrict__ x_u,
        const float* __restrict__ x_i, int NUn, int NIn)
{
    int t = blockIdx.y;
    int Nn = t ? NIn : NUn;
    const float* X = t ? x_i : x_u;
    __shared__ float xs[16][260];
    __shared__ float ws[16][260];
    int tid = threadIdx.x;
    int nb = blockIdx.x * 16;
    for (int i = tid; i < 16 * 256; i += 256) {
        int r = i >> 8, c = i & 255;
        ws[r][c] = g_weff[t * 2 + (r >> 3)][(r & 7) * 256 + c];
    }
    for (int i = tid; i < 16 * 64; i += 256) {
        int r = i >> 6, c = i & 63;
        float4 v = make_float4(0.f, 0.f, 0.f, 0.f);
        if (nb + r < Nn) v = *(const float4*)(X + (long long)(nb + r) * 256 + c * 4);
        *(float4*)(&xs[r][c * 4]) = v;
    }
    __syncthreads();
    int ln = tid >> 4;
    int o  = tid & 15;
    float acc = 0.f;
    #pragma unroll 4
    for (int k = 0; k < 256; k += 4) {
        float4 xv = *(const float4*)(&xs[ln][k]);
        float4 wv = *(const float4*)(&ws[o][k]);
        acc += xv.x * wv.x + xv.y * wv.y + xv.z * wv.z + xv.w * wv.w;
    }
    int node = nb + ln;
    if (node < Nn) {
        int slice = t * 2 + (o >> 3);
        g_a[slice][node * 8 + (o & 7)] = acc + g_beff[slice][o & 7];
    }
}

// ---------------- edge pass 1 (all etypes): exp(score), den, deg ----------
// blockIdx.y = etype. slices: et0 (k=1,q=2), et1 (k=3,q=0), et2 (k=1,q=0)
__global__ void edge1_all_kernel(
        const int* __restrict__ s0, const int* __restrict__ d0,
        const int* __restrict__ s1, const int* __restrict__ d1,
        const int* __restrict__ s2, const int* __restrict__ d2,
        int E0, int E1, int E2)
{
    int et = blockIdx.y;
    const int* src = (et == 0) ? s0 : (et == 1) ? s1 : s2;
    const int* dst = (et == 0) ? d0 : (et == 1) ? d1 : d2;
    int E       = (et == 0) ? E0 : (et == 1) ? E1 : E2;
    int sliceS  = (et == 0) ? 1  : (et == 1) ? 3  : 1;
    int sliceD  = (et == 0) ? 2  : 0;
    int idx = blockIdx.x * blockDim.x + threadIdx.x;
    if (idx >= E * 8) return;
    int e = idx >> 3, h = idx & 7;
    int s = src[e], d = dst[e];
    float sc = (g_a[sliceS][s * 8 + h] + g_a[sliceD][d * 8 + h]) * 0.125f;
    float w = expf(sc);
    g_w[et][e * 8 + h] = w;
    atomicAdd(&g_den[et][d * 8 + h], w);
    if (h == 0) atomicAdd(&g_deg[et][d], 1.0f);
}

// ---------------- edge pass 2 (all etypes): normalized scatter into out ----
// blockIdx.y = etype. vsel {0,1,0}; outBase: et0 -> item region, else user.
__global__ void __launch_bounds__(256) edge2_all_kernel(
        const int* __restrict__ s0, const int* __restrict__ d0,
        const int* __restrict__ s1, const int* __restrict__ d1,
        const int* __restrict__ s2, const int* __restrict__ d2,
        int E0, int E1, int E2, float* __restrict__ out, int NUn)
{
    int et = blockIdx.y;
    const int* src = (et == 0) ? s0 : (et == 1) ? s1 : s2;
    const int* dst = (et == 0) ? d0 : (et == 1) ? d1 : d2;
    int E    = (et == 0) ? E0 : (et == 1) ? E1 : E2;
    int vsel = (et == 1) ? 1 : 0;
    float* outBase = (et == 0) ? out + (long long)NUn * 512 : out;

    int gw = (int)((blockIdx.x * blockDim.x + threadIdx.x) >> 5);
    int lane = threadIdx.x & 31;
    if (gw >= E) return;
    int s = __ldg(src + gw), d = __ldg(dst + gw);
    const float* vrow = g_v[vsel] + (long long)s * 512;
    float wv = 0.f;
    if (lane < 8) {
        float den = g_den[et][d * 8 + lane];
        float dg  = g_deg[et][d];
        wv = g_w[et][gw * 8 + lane] / (den * dg);
    }
    float* nrow = outBase + (long long)d * 512;
    #pragma unroll
    for (int c = 0; c < 4; c++) {
        int off = (c * 32 + lane) * 4;
        float4 v = *(const float4*)(vrow + off);
        float wh = __shfl_sync(0xffffffffu, wv, off >> 6);
        float4 m = make_float4(v.x * wh, v.y * wh, v.z * wh, v.w * wh);
        atomicAdd((float4*)(nrow + off), m);
    }
}

// ---------------- launch: 5 kernels, single stream ----------------
extern "C" void kernel_launch(void* const* d_in, const int* in_sizes, int n_in,
                              void* d_out, int out_size)
{
    const float* x_u  = (const float*)d_in[0];
    const float* x_i  = (const float*)d_in[1];
    const float* Wq_u = (const float*)d_in[2];  const float* bq_u = (const float*)d_in[3];
    const float* Wk_u = (const float*)d_in[4];  const float* bk_u = (const float*)d_in[5];
    const float* Wv_u = (const float*)d_in[6];  const float* bv_u = (const float*)d_in[7];
    const float* Wq_i = (const float*)d_in[8];  const float* bq_i = (const float*)d_in[9];
    const float* Wk_i = (const float*)d_in[10]; const float* bk_i = (const float*)d_in[11];
    const float* Wv_i = (const float*)d_in[12]; const float* bv_i = (const float*)d_in[13];
    const float* wa_u = (const float*)d_in[14];
    const float* wa_i = (const float*)d_in[15];
    const int* src_c  = (const int*)d_in[16];   const int* dst_c  = (const int*)d_in[17];
    const int* src_cb = (const int*)d_in[18];   const int* dst_cb = (const int*)d_in[19];
    const int* src_f  = (const int*)d_in[20];   const int* dst_f  = (const int*)d_in[21];
    int NUn = in_sizes[0] / 256;
    int NIn = in_sizes[1] / 256;
    int E0 = in_sizes[16], E1 = in_sizes[18], E2 = in_sizes[20];
    float* out = (float*)d_out;

    prep_kernel<<<1057 + 1024, 256>>>(out, (long long)(NUn + NIn) * 512,
                                      Wv_u, Wv_i, Wq_u, Wk_u, Wq_i, Wk_i,
                                      bq_u, bk_u, bq_i, bk_i, wa_u, wa_i);

    int Mmax = NUn > NIn ? NUn : NIn;
    hgemm2_kernel<<<dim3(4, (Mmax + 127) / 128, 2), 256>>>(x_u, x_i, bv_u, bv_i, NUn, NIn);

    attn_scalar_kernel<<<dim3((Mmax + 15) / 16, 2), 256>>>(x_u, x_i, NUn, NIn);

    int Emax = E0 > E1 ? E0 : E1; if (E2 > Emax) Emax = E2;
    edge1_all_kernel<<<dim3((Emax * 8 + 255) / 256, 3), 256>>>(
        src_c, dst_c, src_cb, dst_cb, src_f, dst_f, E0, E1, E2);

    edge2_all_kernel<<<dim3((Emax * 32 + 255) / 256, 3), 256>>>(
        src_c, dst_c, src_cb, dst_cb, src_f, dst_f, E0, E1, E2, out, NUn);
}